// round 9
// baseline (speedup 1.0000x reference)
#include <cuda_runtime.h>
#include <cuda_bf16.h>
#include <cstdint>

// LGMLoss on GB300 — Round 9: two kernels, no device barrier, no cross-CTA tail.
// K1: precompute B' (swizzled chunks) + K + invden + passthrough.
// K2: grid 128 x 512thr, BM=16, BN=256(full), depth-3 bulk-copy B pipeline
//     issued at t=0, 16 warps of 16x16 HMMA tiles, fused loss epilogue.

#define B_BATCH 2048
#define C_CLS   256
#define F_DIM   256
#define ALPHA_F 0.1f
#define EPS_F   1e-8f

#define BM      16
#define NCHUNK  4              // K split: 4 chunks of 128 bf16 (64 features)
#define NBUF    3              // B smem buffers
#define STR     272            // A smem row stride (256B + 16 pad)
#define B_CHUNK_BYTES 65536    // 256 rows x 256B

// ---------------- device scratch ----------------
// B' pre-swizzled, chunk-major: [4][256 rows][64 words]; word = bf16x2 (iv, -2m*iv)
__device__ uint32_t g_Bchunks[NCHUNK * C_CLS * 64];
__device__ float g_K[C_CLS];
__device__ float g_invden[C_CLS];

// ---------------- helpers ----------------
__device__ __forceinline__ uint32_t smem_u32(const void* p) {
    uint32_t a;
    asm("{ .reg .u64 t; cvta.to.shared.u64 t, %1; cvt.u32.u64 %0, t; }"
        : "=r"(a) : "l"(p));
    return a;
}
__device__ __forceinline__ void ldmatrix_x4(uint32_t* r, uint32_t addr) {
    asm volatile("ldmatrix.sync.aligned.m8n8.x4.shared.b16 {%0,%1,%2,%3}, [%4];"
                 : "=r"(r[0]), "=r"(r[1]), "=r"(r[2]), "=r"(r[3]) : "r"(addr));
}
__device__ __forceinline__ void mma16816(float* d, const uint32_t* a,
                                         uint32_t b0, uint32_t b1) {
    asm volatile(
        "mma.sync.aligned.m16n8k16.row.col.f32.bf16.bf16.f32 "
        "{%0,%1,%2,%3}, {%4,%5,%6,%7}, {%8,%9}, {%0,%1,%2,%3};"
        : "+f"(d[0]), "+f"(d[1]), "+f"(d[2]), "+f"(d[3])
        : "r"(a[0]), "r"(a[1]), "r"(a[2]), "r"(a[3]), "r"(b0), "r"(b1));
}
__device__ __forceinline__ uint32_t pack_pair(float x) {
    __nv_bfloat162 p = __floats2bfloat162_rn(x * x, x);   // (x^2, x)
    return *(uint32_t*)&p;
}
#define MBAR_INIT(a, n) \
    asm volatile("mbarrier.init.shared.b64 [%0], %1;" :: "r"(a), "r"(n) : "memory")
#define MBAR_EXPECT_TX(a, tx) \
    asm volatile("mbarrier.arrive.expect_tx.shared.b64 _, [%0], %1;" \
                 :: "r"(a), "r"(tx) : "memory")
#define MBAR_WAIT(a, ph) do { \
    asm volatile("{ .reg .pred P; WL%=: mbarrier.try_wait.parity.acquire.cta.shared::cta.b64 P, [%0], %1, 0x989680;" \
                 " @P bra WD%=; bra WL%=; WD%=: }" :: "r"(a), "r"(ph) : "memory"); \
} while (0)
__device__ __forceinline__ void bulk_copy(uint32_t dst, const void* src,
                                          uint32_t bytes, uint32_t mbar) {
    asm volatile(
        "cp.async.bulk.shared::cluster.global.mbarrier::complete_tx::bytes "
        "[%0], [%1], %2, [%3];"
        :: "r"(dst), "l"(src), "r"(bytes), "r"(mbar) : "memory");
}

// ---------------------------------------------------------------------------
// Kernel 1: per-class precompute -> swizzled B chunks, K[c], invden[c],
// plus means/vars passthrough. grid = 256, block = 256 (t = feature).
// (Indexing identical to R6 — proven correct.)
// ---------------------------------------------------------------------------
__global__ __launch_bounds__(256) void precompute_kernel(
    const float* __restrict__ means,
    const float* __restrict__ vars_,
    float* __restrict__ out) {
    int c = blockIdx.x;
    int t = threadIdx.x;
    float v = vars_[c * F_DIM + t];
    float m = means[c * F_DIM + t];
    float iv = 1.0f / (v + EPS_F);
    __nv_bfloat162 pr2 = __floats2bfloat162_rn(iv, -2.0f * m * iv);
    {   // chunk-major, seg-swizzled store: feature t -> chunk t>>6, pair p=t&63
        int ci = t >> 6, p = t & 63;
        int w = ci * (C_CLS * 64) + c * 64 + ((((p >> 2) ^ (c & 7)) << 2) | (p & 3));
        g_Bchunks[w] = *(uint32_t*)&pr2;
    }
    out[B_BATCH + c * F_DIM + t] = m;                        // passthrough
    out[B_BATCH + C_CLS * F_DIM + c * F_DIM + t] = v;

    float ks = m * m * iv;
    float pr = v;
    #pragma unroll
    for (int o = 16; o > 0; o >>= 1) {
        ks += __shfl_xor_sync(0xffffffffu, ks, o);
        pr *= __shfl_xor_sync(0xffffffffu, pr, o);
    }
    __shared__ float wsum[8], wprod[8];
    int w = t >> 5, l = t & 31;
    if (l == 0) { wsum[w] = ks; wprod[w] = pr; }
    __syncthreads();
    if (t == 0) {
        float K = 0.0f, det = 1.0f;
        #pragma unroll
        for (int i = 0; i < 8; i++) { K += wsum[i]; det *= wprod[i]; }
        g_K[c] = K;
        g_invden[c] = 1.0f / (det * det + EPS_F);
    }
}

// ---------------------------------------------------------------------------
// Kernel 2: fused HMMA GEMM + loss. grid = 128 x 512 threads (16 warps).
// Warp w: cols [w*16, w*16+16), rows 0..15 (acc 2 x n8 tiles).
// Smem (bytes):
//   0: sK(1K) | 1024: sInv(1K) | 2048: sPS(1K)+sPP(1K) | 4096: mbar[4]
//   4224: A 4 x 4352 | 22528: B 3 x 65536   total 219136
// ---------------------------------------------------------------------------
#define SM_KOFF 0
#define SM_IOFF 1024
#define SM_RED  2048
#define SM_MBAR 4096
#define SM_A    4224
#define A_BUFSZ 4352
#define SM_B    22528
#define SMEM_TOTAL 219136

__global__ __launch_bounds__(512, 1) void lgm_gemm_kernel(
    const float* __restrict__ feat,
    const int* __restrict__ labels,
    float* __restrict__ out) {
    extern __shared__ char smem[];
    const int tid  = threadIdx.x;
    const int wid  = tid >> 5;
    const int lane = tid & 31;
    const int bRow0 = blockIdx.x * BM;
    const uint32_t sbase = smem_u32(smem);

    float* sK   = (float*)(smem + SM_KOFF);
    float* sInv = (float*)(smem + SM_IOFF);
    float* sPS  = (float*)(smem + SM_RED);          // [16 rows][16 warps]
    float* sPP  = sPS + 256;

    // t=0: init mbarriers and fire ALL initial B bulk copies (B' already valid
    // — the graph edge from K1 is the barrier).
    if (tid == 0) {
        #pragma unroll
        for (int i = 0; i < NCHUNK; i++) MBAR_INIT(sbase + SM_MBAR + i * 8, 1);
        asm volatile("fence.proxy.async;" ::: "memory");
        #pragma unroll
        for (int ci = 0; ci < NBUF; ci++) {
            MBAR_EXPECT_TX(sbase + SM_MBAR + ci * 8, B_CHUNK_BYTES);
            bulk_copy(sbase + SM_B + ci * B_CHUNK_BYTES,
                      g_Bchunks + ci * (C_CLS * 64), B_CHUNK_BYTES,
                      sbase + SM_MBAR + ci * 8);
        }
    }

    // A prefetch + stage: all 4 chunks. Threads [0,256): chunks 0,2;
    // threads [256,512): chunks 1,3. 2 float4 per thread.
    const float4* featv = (const float4*)feat;      // 64 float4 per row
    {
        int u  = tid >> 8;                 // 0/1
        int t2 = tid & 255;
        int ar = t2 >> 4, as = t2 & 15;
        #pragma unroll
        for (int j = 0; j < 2; j++) {
            int ci = u + j * 2;
            float4 v = featv[(size_t)(bRow0 + ar) * 64 + ci * 16 + as];
            uint4 w;
            w.x = pack_pair(v.x); w.y = pack_pair(v.y);
            w.z = pack_pair(v.z); w.w = pack_pair(v.w);
            *(uint4*)(smem + SM_A + ci * A_BUFSZ + ar * STR + as * 16) = w;
        }
    }
    // per-class constants
    if (tid < 256) sK[tid] = g_K[tid];
    else           sInv[tid - 256] = g_invden[tid - 256];
    __syncthreads();    // A staged + mbar inits visible

    // ---------------- mainloop ----------------
    const int wn = wid;                    // cols wn*16 .. +15
    float acc[2][4] = {};
    #pragma unroll
    for (int ci = 0; ci < NCHUNK; ci++) {
        const int buf = ci % NBUF;
        MBAR_WAIT(sbase + SM_MBAR + ci * 8, 0);
        const uint32_t sAu = sbase + SM_A + ci * A_BUFSZ;
        const uint32_t sBu = sbase + SM_B + buf * B_CHUNK_BYTES;
        #pragma unroll
        for (int ks = 0; ks < 8; ks++) {
            uint32_t a[4], b[4];
            ldmatrix_x4(a, sAu + (uint32_t)(lane & 15) * STR
                           + (uint32_t)(ks * 32 + ((lane >> 4) & 1) * 16));
            {
                int brow = wn * 16 + (lane & 7) + ((lane >> 4) & 1) * 8;
                int bseg = ks * 2 + ((lane >> 3) & 1);
                ldmatrix_x4(b, sBu + (uint32_t)(brow * 256
                                  + ((bseg ^ (brow & 7)) << 4)));
            }
            mma16816(acc[0], a, b[0], b[1]);
            mma16816(acc[1], a, b[2], b[3]);
        }
        if (ci == 0) {                     // reissue chunk 3 into buf 0
            __syncthreads();
            if (tid == 0) {
                MBAR_EXPECT_TX(sbase + SM_MBAR + 3 * 8, B_CHUNK_BYTES);
                bulk_copy(sbase + SM_B, g_Bchunks + 3 * (C_CLS * 64),
                          B_CHUNK_BYTES, sbase + SM_MBAR + 3 * 8);
            }
        }
    }

    // ---------------- epilogue: prob + fused loss ----------------
    const int r0 = lane >> 2;
    const int lbl0 = labels[bRow0 + r0];
    const int lbl1 = labels[bRow0 + r0 + 8];
    float s0 = 0.f, s1 = 0.f, pl0 = 0.f, pl1 = 0.f;
    #pragma unroll
    for (int nt = 0; nt < 2; nt++) {
        int c0 = wn * 16 + nt * 8 + (lane & 3) * 2;
        int c1 = c0 + 1;
        float k0 = sK[c0], k1 = sK[c1];
        float i0 = sInv[c0], i1 = sInv[c1];
        {
            float d0 = 0.5f * (acc[nt][0] + k0);
            float d1 = 0.5f * (acc[nt][1] + k1);
            if (c0 == lbl0) d0 *= (1.0f + ALPHA_F);
            if (c1 == lbl0) d1 *= (1.0f + ALPHA_F);
            float p0 = __expf(-d0) * i0;
            float p1 = __expf(-d1) * i1;
            s0 += p0 + p1;
            if (c0 == lbl0) pl0 += p0;
            if (c1 == lbl0) pl0 += p1;
        }
        {
            float d0 = 0.5f * (acc[nt][2] + k0);
            float d1 = 0.5f * (acc[nt][3] + k1);
            if (c0 == lbl1) d0 *= (1.0f + ALPHA_F);
            if (c1 == lbl1) d1 *= (1.0f + ALPHA_F);
            float p0 = __expf(-d0) * i0;
            float p1 = __expf(-d1) * i1;
            s1 += p0 + p1;
            if (c0 == lbl1) pl1 += p0;
            if (c1 == lbl1) pl1 += p1;
        }
    }
    #pragma unroll
    for (int o = 1; o < 4; o <<= 1) {
        s0  += __shfl_xor_sync(0xffffffffu, s0, o);
        s1  += __shfl_xor_sync(0xffffffffu, s1, o);
        pl0 += __shfl_xor_sync(0xffffffffu, pl0, o);
        pl1 += __shfl_xor_sync(0xffffffffu, pl1, o);
    }
    if ((lane & 3) == 0) {
        sPS[r0 * 16 + wn]       = s0;
        sPS[(r0 + 8) * 16 + wn] = s1;
        sPP[r0 * 16 + wn]       = pl0;
        sPP[(r0 + 8) * 16 + wn] = pl1;
    }
    __syncthreads();
    if (tid < BM) {
        float s = 0.f, pl = 0.f;
        #pragma unroll
        for (int w = 0; w < 16; w++) {
            s  += sPS[tid * 16 + w];
            pl += sPP[tid * 16 + w];
        }
        out[bRow0 + tid] = -logf(pl / (s + EPS_F) + EPS_F);
    }
}

// ---------------------------------------------------------------------------
extern "C" void kernel_launch(void* const* d_in, const int* in_sizes, int n_in,
                              void* d_out, int out_size) {
    const float* feat   = (const float*)d_in[0];
    const int*   labels = (const int*)d_in[1];
    const float* means  = (const float*)d_in[2];
    const float* vars_  = (const float*)d_in[3];
    float* out = (float*)d_out;

    cudaFuncSetAttribute(lgm_gemm_kernel,
                         cudaFuncAttributeMaxDynamicSharedMemorySize, SMEM_TOTAL);

    precompute_kernel<<<C_CLS, 256>>>(means, vars_, out);
    lgm_gemm_kernel<<<B_BATCH / BM, 512, SMEM_TOTAL>>>(feat, labels, out);
}

// round 10
// speedup vs baseline: 2.0627x; 2.0627x over previous
#include <cuda_runtime.h>
#include <cuda_bf16.h>
#include <cstdint>

// LGMLoss on GB300 — Round 10: single fused kernel, clusters of 2.
// Each CTA: 32 rows x 128 cols (N-split by cluster rank); DSMEM combine.
// grid 128 CTAs (64 clusters) x 256 threads; epoch barrier before B stream.

#define B_BATCH 2048
#define C_CLS   256
#define F_DIM   256
#define ALPHA_F 0.1f
#define EPS_F   1e-8f

#define BM      32
#define NCHUNK  4              // K split: 4 chunks of 128 bf16 (64 features)
#define STR     272            // A smem row stride (256B + 16 pad)
#define B_CHUNK_BYTES 32768    // 128 rows x 256B

// ---------------- device scratch ----------------
// B' pre-swizzled, chunk-major: [4][256 rows][64 words]; word = bf16x2 (iv,-2m*iv)
__device__ uint32_t g_Bchunks[NCHUNK * C_CLS * 64];
__device__ float g_K[C_CLS];
__device__ float g_invden[C_CLS];
__device__ unsigned int g_bar;          // epoch barrier (monotonic, never reset)

// ---------------- helpers ----------------
__device__ __forceinline__ uint32_t smem_u32(const void* p) {
    uint32_t a;
    asm("{ .reg .u64 t; cvta.to.shared.u64 t, %1; cvt.u32.u64 %0, t; }"
        : "=r"(a) : "l"(p));
    return a;
}
__device__ __forceinline__ void ldmatrix_x4(uint32_t* r, uint32_t addr) {
    asm volatile("ldmatrix.sync.aligned.m8n8.x4.shared.b16 {%0,%1,%2,%3}, [%4];"
                 : "=r"(r[0]), "=r"(r[1]), "=r"(r[2]), "=r"(r[3]) : "r"(addr));
}
__device__ __forceinline__ void mma16816(float* d, const uint32_t* a,
                                         uint32_t b0, uint32_t b1) {
    asm volatile(
        "mma.sync.aligned.m16n8k16.row.col.f32.bf16.bf16.f32 "
        "{%0,%1,%2,%3}, {%4,%5,%6,%7}, {%8,%9}, {%0,%1,%2,%3};"
        : "+f"(d[0]), "+f"(d[1]), "+f"(d[2]), "+f"(d[3])
        : "r"(a[0]), "r"(a[1]), "r"(a[2]), "r"(a[3]), "r"(b0), "r"(b1));
}
__device__ __forceinline__ uint32_t pack_pair(float x) {
    __nv_bfloat162 p = __floats2bfloat162_rn(x * x, x);   // (x^2, x)
    return *(uint32_t*)&p;
}
#define MBAR_INIT(a, n) \
    asm volatile("mbarrier.init.shared.b64 [%0], %1;" :: "r"(a), "r"(n) : "memory")
#define MBAR_EXPECT_TX(a, tx) \
    asm volatile("mbarrier.arrive.expect_tx.shared.b64 _, [%0], %1;" \
                 :: "r"(a), "r"(tx) : "memory")
#define MBAR_WAIT(a, ph) do { \
    asm volatile("{ .reg .pred P; WL%=: mbarrier.try_wait.parity.acquire.cta.shared::cta.b64 P, [%0], %1, 0x989680;" \
                 " @P bra WD%=; bra WL%=; WD%=: }" :: "r"(a), "r"(ph) : "memory"); \
} while (0)
__device__ __forceinline__ void bulk_copy(uint32_t dst, const void* src,
                                          uint32_t bytes, uint32_t mbar) {
    asm volatile(
        "cp.async.bulk.shared::cluster.global.mbarrier::complete_tx::bytes "
        "[%0], [%1], %2, [%3];"
        :: "r"(dst), "l"(src), "r"(bytes), "r"(mbar) : "memory");
}
#define CLUSTER_ARRIVE() asm volatile("barrier.cluster.arrive.aligned;" ::: "memory")
#define CLUSTER_WAIT()   asm volatile("barrier.cluster.wait.aligned;" ::: "memory")
__device__ __forceinline__ uint32_t mapa_peer(uint32_t addr, uint32_t rank) {
    uint32_t r;
    asm("mapa.shared::cluster.u32 %0, %1, %2;" : "=r"(r) : "r"(addr), "r"(rank));
    return r;
}
__device__ __forceinline__ float ld_dsmem_f32(uint32_t addr) {
    float v;
    asm volatile("ld.shared::cluster.f32 %0, [%1];" : "=f"(v) : "r"(addr));
    return v;
}

// ---------------------------------------------------------------------------
// Smem layout (bytes):
//   0: sK(1K) | 1024: sInv(1K) | 2048: sPS(1K)+sPP(1K) | 4096: sX(256B)
//   4352: mbar[4] | 4608: A 4 x 8704 | 39424: B 4 x 32768   total 170496
// ---------------------------------------------------------------------------
#define SM_KOFF 0
#define SM_IOFF 1024
#define SM_RED  2048
#define SM_X    4096
#define SM_MBAR 4352
#define SM_A    4608
#define A_BUFSZ 8704
#define SM_B    39424
#define SMEM_TOTAL 170496

__global__ __launch_bounds__(256, 1) __cluster_dims__(2, 1, 1)
void lgm_fused_kernel(
    const float* __restrict__ feat,
    const int* __restrict__ labels,
    const float* __restrict__ means,
    const float* __restrict__ vars_,
    float* __restrict__ out) {
    extern __shared__ char smem[];
    const int tid  = threadIdx.x;
    const int wid  = tid >> 5;
    const int lane = tid & 31;
    const int bid  = blockIdx.x;
    const int rank = bid & 1;             // cluster rank = col half
    const int grp  = bid >> 1;            // row group (32 rows)
    const int bRow0 = grp * BM;
    const uint32_t sbase = smem_u32(smem);

    float* sK   = (float*)(smem + SM_KOFF);
    float* sInv = (float*)(smem + SM_IOFF);
    float* sPS  = (float*)(smem + SM_RED);          // [32 rows][8 warps]
    float* sPP  = sPS + 256;
    float* sXs  = (float*)(smem + SM_X);            // [32] row partial sum
    float* sXp  = sXs + 32;                         // [32] row partial p_lbl

    if (tid == 0) {
        #pragma unroll
        for (int i = 0; i < NCHUNK; i++) MBAR_INIT(sbase + SM_MBAR + i * 8, 1);
    }

    // ---- A prefetch: all 4 chunks, 8 float4/thread (LDGs fly during phase 1)
    const float4* featv = (const float4*)feat;      // 64 float4 per row
    const int ar = tid >> 3, as = tid & 7;          // 32 rows x 8 thread-cols
    float4 aReg[8];
    #pragma unroll
    for (int ci = 0; ci < NCHUNK; ci++) {
        aReg[ci * 2 + 0] = featv[(size_t)(bRow0 + ar) * 64 + ci * 16 + as];
        aReg[ci * 2 + 1] = featv[(size_t)(bRow0 + ar) * 64 + ci * 16 + as + 8];
    }

    // ---------------- phase 1: per-class precompute (2 classes/CTA) --------
    {
        const int half = tid >> 7;            // 0/1 -> class
        const int tf   = tid & 127;           // feature-pair index
        const int c    = 2 * bid + half;
        float2 mv = ((const float2*)means)[c * 128 + tf];
        float2 vv = ((const float2*)vars_)[c * 128 + tf];
        float iv0 = 1.0f / (vv.x + EPS_F);
        float iv1 = 1.0f / (vv.y + EPS_F);
        __nv_bfloat162 p0 = __floats2bfloat162_rn(iv0, -2.0f * mv.x * iv0);
        __nv_bfloat162 p1 = __floats2bfloat162_rn(iv1, -2.0f * mv.y * iv1);
        {   // swizzled chunk-major store (p even -> consecutive words)
            int f = 2 * tf;
            int ci = f >> 6, p = f & 63;
            int idx = ci * (C_CLS * 64) + c * 64
                    + ((((p >> 2) ^ (c & 7)) << 2) | (p & 3));
            uint2 w;
            w.x = *(uint32_t*)&p0;
            w.y = *(uint32_t*)&p1;
            *(uint2*)&g_Bchunks[idx] = w;
        }
        ((float2*)(out + B_BATCH))[c * 128 + tf] = mv;           // passthrough
        ((float2*)(out + B_BATCH + C_CLS * F_DIM))[c * 128 + tf] = vv;

        float ks = mv.x * mv.x * iv0 + mv.y * mv.y * iv1;
        float pr = vv.x * vv.y;
        #pragma unroll
        for (int o = 16; o > 0; o >>= 1) {
            ks += __shfl_xor_sync(0xffffffffu, ks, o);
            pr *= __shfl_xor_sync(0xffffffffu, pr, o);
        }
        if (lane == 0) { sPS[wid] = ks; sPS[16 + wid] = pr; }    // reuse sPS
        __syncthreads();
        if (tf == 0) {
            float K = 0.0f, det = 1.0f;
            #pragma unroll
            for (int i = 0; i < 4; i++) {
                K += sPS[half * 4 + i];
                det *= sPS[16 + half * 4 + i];
            }
            g_K[c] = K;
            g_invden[c] = 1.0f / (det * det + EPS_F);
        }
    }
    // stage all A chunks
    #pragma unroll
    for (int u = 0; u < 8; u++) {
        int ci = u >> 1, j = u & 1;
        float4 v = aReg[u];
        uint4 w;
        w.x = pack_pair(v.x); w.y = pack_pair(v.y);
        w.z = pack_pair(v.z); w.w = pack_pair(v.w);
        *(uint4*)(smem + SM_A + ci * A_BUFSZ + ar * STR + (as + j * 8) * 16) = w;
    }

    // ---------------- device-wide epoch barrier ----------------
    const int start = bid & 3;            // rotated chunk order
    __syncthreads();
    if (tid == 0) {
        __threadfence();
        unsigned tk = atomicAdd(&g_bar, 1u);
        unsigned target = (tk & ~127u) + 128u;
        unsigned cur;
        do {
            asm volatile("ld.acquire.gpu.global.b32 %0, [%1];"
                         : "=r"(cur) : "l"(&g_bar));
        } while (cur < target);
        asm volatile("fence.proxy.async;" ::: "memory");
        #pragma unroll
        for (int i = 0; i < NCHUNK; i++) {
            int ci = (start + i) & 3;
            uint32_t mb = sbase + SM_MBAR + ci * 8;
            MBAR_EXPECT_TX(mb, B_CHUNK_BYTES);
            bulk_copy(sbase + SM_B + ci * B_CHUNK_BYTES,
                      g_Bchunks + ci * (C_CLS * 64) + rank * (128 * 64),
                      B_CHUNK_BYTES, mb);
        }
    }
    __syncthreads();
    sK[tid]   = g_K[tid];                 // valid after barrier
    sInv[tid] = g_invden[tid];

    // ---------------- phase 2: GEMM mainloop ----------------
    // warp wid: local cols [wid*16, wid*16+16), rows 0..31 (2 m16 tiles)
    float acc[2][2][4] = {};
    #pragma unroll
    for (int i = 0; i < NCHUNK; i++) {
        const int ci = (start + i) & 3;
        MBAR_WAIT(sbase + SM_MBAR + ci * 8, 0);
        const uint32_t sAu = sbase + SM_A + ci * A_BUFSZ;
        const uint32_t sBu = sbase + SM_B + ci * B_CHUNK_BYTES;
        #pragma unroll
        for (int ks = 0; ks < 8; ks++) {
            uint32_t a[2][4], b[4];
            #pragma unroll
            for (int mt = 0; mt < 2; mt++)
                ldmatrix_x4(a[mt], sAu + (uint32_t)(mt * 16 + (lane & 15)) * STR
                               + (uint32_t)(ks * 32 + ((lane >> 4) & 1) * 16));
            {
                int brow = wid * 16 + (lane & 7) + ((lane >> 4) & 1) * 8;
                int bseg = ks * 2 + ((lane >> 3) & 1);
                ldmatrix_x4(b, sBu + (uint32_t)(brow * 256
                                  + ((bseg ^ (brow & 7)) << 4)));
            }
            #pragma unroll
            for (int mt = 0; mt < 2; mt++) {
                mma16816(acc[mt][0], a[mt], b[0], b[1]);
                mma16816(acc[mt][1], a[mt], b[2], b[3]);
            }
        }
    }

    // ---------------- epilogue: prob + partial row sums ----------------
    const int r0 = lane >> 2;
    const int colBase = rank * 128 + wid * 16;
    float sums[2][2] = {{0.f,0.f},{0.f,0.f}};
    float pls [2][2] = {{0.f,0.f},{0.f,0.f}};
    int lbls[2][2];
    #pragma unroll
    for (int mt = 0; mt < 2; mt++) {
        lbls[mt][0] = labels[bRow0 + mt * 16 + r0];
        lbls[mt][1] = labels[bRow0 + mt * 16 + r0 + 8];
    }
    #pragma unroll
    for (int nt = 0; nt < 2; nt++) {
        int c0 = colBase + nt * 8 + (lane & 3) * 2;
        int c1 = c0 + 1;
        float k0 = sK[c0], k1 = sK[c1];
        float i0 = sInv[c0], i1 = sInv[c1];
        #pragma unroll
        for (int mt = 0; mt < 2; mt++) {
            #pragma unroll
            for (int h = 0; h < 2; h++) {
                int lbl = lbls[mt][h];
                float d0 = 0.5f * (acc[mt][nt][h * 2 + 0] + k0);
                float d1 = 0.5f * (acc[mt][nt][h * 2 + 1] + k1);
                if (c0 == lbl) d0 *= (1.0f + ALPHA_F);
                if (c1 == lbl) d1 *= (1.0f + ALPHA_F);
                float p0 = __expf(-d0) * i0;
                float p1 = __expf(-d1) * i1;
                sums[mt][h] += p0 + p1;
                if (c0 == lbl) pls[mt][h] += p0;
                if (c1 == lbl) pls[mt][h] += p1;
            }
        }
    }
    #pragma unroll
    for (int o = 1; o < 4; o <<= 1) {
        #pragma unroll
        for (int mt = 0; mt < 2; mt++) {
            #pragma unroll
            for (int h = 0; h < 2; h++) {
                sums[mt][h] += __shfl_xor_sync(0xffffffffu, sums[mt][h], o);
                pls [mt][h] += __shfl_xor_sync(0xffffffffu, pls [mt][h], o);
            }
        }
    }
    __syncthreads();                      // sPS free from phase-1 reuse
    if ((lane & 3) == 0) {
        #pragma unroll
        for (int mt = 0; mt < 2; mt++) {
            #pragma unroll
            for (int h = 0; h < 2; h++) {
                int rloc = mt * 16 + r0 + h * 8;
                sPS[rloc * 8 + wid] = sums[mt][h];
                sPP[rloc * 8 + wid] = pls[mt][h];
            }
        }
    }
    __syncthreads();
    if (tid < BM) {                       // in-CTA combine -> half partials
        float s = 0.f, pl = 0.f;
        #pragma unroll
        for (int w = 0; w < 8; w++) {
            s  += sPS[tid * 8 + w];
            pl += sPP[tid * 8 + w];
        }
        sXs[tid] = s;
        sXp[tid] = pl;
    }

    // ---------------- cross-rank DSMEM combine ----------------
    CLUSTER_ARRIVE();
    CLUSTER_WAIT();                       // peer's sX visible
    if (rank == 0 && tid < BM) {
        uint32_t peerS = mapa_peer(sbase + SM_X + tid * 4, 1);
        uint32_t peerP = mapa_peer(sbase + SM_X + 128 + tid * 4, 1);
        float s  = sXs[tid] + ld_dsmem_f32(peerS);
        float pl = sXp[tid] + ld_dsmem_f32(peerP);
        out[bRow0 + tid] = -logf(pl / (s + EPS_F) + EPS_F);
    }
    CLUSTER_ARRIVE();                     // keep peer smem alive until read
    CLUSTER_WAIT();
}

// ---------------------------------------------------------------------------
extern "C" void kernel_launch(void* const* d_in, const int* in_sizes, int n_in,
                              void* d_out, int out_size) {
    const float* feat   = (const float*)d_in[0];
    const int*   labels = (const int*)d_in[1];
    const float* means  = (const float*)d_in[2];
    const float* vars_  = (const float*)d_in[3];
    float* out = (float*)d_out;

    cudaFuncSetAttribute(lgm_fused_kernel,
                         cudaFuncAttributeMaxDynamicSharedMemorySize, SMEM_TOTAL);

    lgm_fused_kernel<<<128, 256, SMEM_TOTAL>>>(feat, labels, means, vars_, out);
}